// round 4
// baseline (speedup 1.0000x reference)
#include <cuda_runtime.h>

// Problem constants
#define TT    4096
#define EMB   1024
#define H2    512
#define G4    2048       // 4 * H2
#define NTAGS 5
#define START 3
#define STOP  4
#define NEGV  -10000.0f

// Recurrence: 32 CTAs per direction, 16 hidden units (64 gate rows) each
#define NCTA   32
#define HPER   16
#define CHUNK  128       // GEMM t-tile = gating granularity
#define NCHUNK (TT / CHUNK)   // 32
#define NBLK   16        // gate-col 128-blocks per row (2048/128)
#define SENTB  0x7FC00000u    // NaN sentinel bit pattern

// -------------------- scratch (static device globals; no allocs) ------------
__device__ float d_G[2][TT * G4];         // input-gate preactivations (64 MB)
__device__ float d_h[2][TT * H2];         // hidden states (16 MB), sentinel-init
__device__ float d_feats[TT * NTAGS];     // tag scores
__device__ int   d_cnt[2][NCHUNK];        // per-(dir,chunk) GEMM completion

// -------------------- helpers ----------------------------------------------
__device__ __forceinline__ unsigned ld_acq_u32(const unsigned* p) {
    unsigned v;
    asm volatile("ld.acquire.gpu.global.b32 %0, [%1];" : "=r"(v) : "l"(p) : "memory");
    return v;
}
__device__ __forceinline__ int ld_acq_s32(const int* p) {
    int v;
    asm volatile("ld.acquire.gpu.global.b32 %0, [%1];" : "=r"(v) : "l"(p) : "memory");
    return v;
}
__device__ __forceinline__ void st_rel_f32(float* p, float v) {
    asm volatile("st.release.gpu.global.f32 [%0], %1;" :: "l"(p), "f"(v) : "memory");
}
__device__ __forceinline__ void red_rel_add(int* p) {
    asm volatile("red.release.gpu.global.add.u32 [%0], 1;" :: "l"(p) : "memory");
}
__device__ __forceinline__ float sigmoidf(float x) {
    return 1.0f / (1.0f + expf(-x));
}

// -------------------- kernel: init sentinels + counters ---------------------
// d_h = 2*4096*512 floats = 1,048,576 uint4
__global__ void k_init() {
    int i = blockIdx.x * blockDim.x + threadIdx.x;
    uint4 s; s.x = SENTB; s.y = SENTB; s.z = SENTB; s.w = SENTB;
    ((uint4*)d_h)[i] = s;
    if (i < 2 * NCHUNK) ((int*)d_cnt)[i] = 0;
}

// -------------------- fused mega-kernel --------------------------------------
// blocks 0..63:    persistent LSTM recurrence (dir = bid>>5, slice = bid&31)
// blocks 64..1087: input GEMM tiles G = embed[sent] @ Wih^T + (bih+bhh),
//                  128(t) x 128(gate) x k16 double-buffered, t-chunk ascending.
__global__ void __launch_bounds__(512, 1) k_main(
    const int*   __restrict__ sent,  const float* __restrict__ embed,
    const float* __restrict__ Wih_f, const float* __restrict__ Whh_f,
    const float* __restrict__ bih_f, const float* __restrict__ bhh_f,
    const float* __restrict__ Wih_b, const float* __restrict__ Whh_b,
    const float* __restrict__ bih_b, const float* __restrict__ bhh_b,
    const float* __restrict__ h0,    const float* __restrict__ c0) {

    __shared__ __align__(16) float smem_buf[8192];   // 32 KB, aliased per role
    int bid = blockIdx.x;
    int tid = threadIdx.x;
    int warp = tid >> 5, lane = tid & 31;

    if (bid < 2 * NCTA) {
        // ================= recurrence CTA =================
        int dir   = bid >> 5;
        int slice = bid & 31;
        int hbase = slice * HPER;
        const float* Whh = dir ? Whh_b : Whh_f;
        const float* Gd  = d_G[dir];
        float* hout = d_h[dir];
        int*   cnt  = d_cnt[dir];

        float* sh    = smem_buf;          // 512 floats: h(t-1)
        float* rec_s = smem_buf + 512;    // 64 row sums

        // this thread's gate row: 4 rows per warp, 8 lanes per row
        int row_local = 4 * warp + (lane >> 3);        // 0..63 == g*16 + j
        int g = row_local >> 4, j = row_local & 15;
        int grow = g * H2 + hbase + j;
        int ksub = lane & 7;                           // k-slice within row

        // Whh slice: 16 float4 per thread (64 weights)
        float4 w4[16];
#pragma unroll
        for (int q = 0; q < 16; q++)
            w4[q] = *(const float4*)(Whh + (size_t)grow * H2 + (ksub + 8 * q) * 4);

        // activation state (warp 0, lanes 0..15)
        float cj = 0.0f;
        bool act = (warp == 0) && (lane < HPER);
        if (act) cj = c0[dir * H2 + hbase + lane];

        for (int t = 0; t < TT; t++) {
            // gate on GEMM chunk completion (once per 128 steps)
            if ((t & (CHUNK - 1)) == 0) {
                if (tid == 0) {
                    int ch = t >> 7;
                    while (ld_acq_s32(&cnt[ch]) < NBLK) { }
                }
                __syncthreads();
            }

            // issue G loads early (L2 latency hides under the h-poll)
            float gv0 = 0.f, gv1 = 0.f, gv2 = 0.f, gv3 = 0.f;
            if (act) {
                const float* Gt = Gd + (size_t)t * G4 + hbase + lane;
                gv0 = Gt[0];  gv1 = Gt[H2];  gv2 = Gt[2 * H2];  gv3 = Gt[3 * H2];
            }

            // obtain h(t-1)
            if (t == 0) {
                sh[tid] = h0[dir * H2 + tid];
                __syncthreads();
            } else {
                const float* hprev = hout + (size_t)(t - 1) * H2;
                if (warp == 0) {
                    // lane s polls producer s's release element (s*16+15)
                    const unsigned* p = (const unsigned*)(hprev + lane * HPER + 15);
                    unsigned v;
                    do { v = ld_acq_u32(p); } while (v == SENTB);
                    sh[lane * HPER + 15] = __uint_as_float(v);
                }
                __syncthreads();
                if ((tid & 15) != 15) sh[tid] = hprev[tid];
                __syncthreads();
            }

            // GEMV: each thread dots 64 h-elems against its weight slice
            const float4* sh4 = (const float4*)sh;
            float a0 = 0.0f, a1 = 0.0f;
#pragma unroll
            for (int q = 0; q < 16; q += 2) {
                float4 hv0 = sh4[ksub + 8 * q];
                float4 hv1 = sh4[ksub + 8 * (q + 1)];
                a0 += w4[q].x * hv0.x + w4[q].y * hv0.y + w4[q].z * hv0.z + w4[q].w * hv0.w;
                a1 += w4[q+1].x * hv1.x + w4[q+1].y * hv1.y + w4[q+1].z * hv1.z + w4[q+1].w * hv1.w;
            }
            float a = a0 + a1;
            a += __shfl_xor_sync(0xffffffffu, a, 1);
            a += __shfl_xor_sync(0xffffffffu, a, 2);
            a += __shfl_xor_sync(0xffffffffu, a, 4);
            if (ksub == 0) rec_s[row_local] = a;
            __syncthreads();

            // activation + h store + release (warp 0)
            if (warp == 0) {
                float hj = 0.0f;
                if (lane < HPER) {
                    float gi = rec_s[0 * HPER + lane] + gv0;
                    float gf = rec_s[1 * HPER + lane] + gv1;
                    float gg = rec_s[2 * HPER + lane] + gv2;
                    float go = rec_s[3 * HPER + lane] + gv3;
                    cj = sigmoidf(gf) * cj + sigmoidf(gi) * tanhf(gg);
                    hj = sigmoidf(go) * tanhf(cj);
                    if (lane < HPER - 1)
                        hout[(size_t)t * H2 + hbase + lane] = hj;
                }
                __syncwarp();
                if (lane == HPER - 1)
                    st_rel_f32(&hout[(size_t)t * H2 + hbase + lane], hj);
            }
        }
    } else {
        // ================= GEMM tile =================
        int gidx = bid - 2 * NCTA;
        int nblk = gidx & 15;
        int dir  = (gidx >> 4) & 1;
        int tblk = gidx >> 5;                 // ascending with bid -> early t first
        const float* W  = dir ? Wih_b : Wih_f;
        const float* b1 = dir ? bih_b : bih_f;
        const float* b2 = dir ? bhh_b : bhh_f;
        float* Gp = d_G[dir];

        int m0 = tblk * CHUNK;
        int n0 = nblk * 128;

        float* As = smem_buf;                 // [2][16*128]
        float* Bs = smem_buf + 4096;          // [2][16*128]

        // loader: one float4 of A and one of B per thread per k-tile
        int lrow = tid >> 2, lkq = tid & 3;
        int srcRow = m0 + lrow;
        if (dir) srcRow = TT - 1 - srcRow;
        int token = sent[srcRow];
        const float* Arow = embed + (size_t)token * EMB;
        const float* Brow = W + (size_t)(n0 + lrow) * EMB;

        int ty = tid >> 5;                    // 0..15 -> m = ty*8..+8
        int tx = tid & 31;                    // 0..31 -> n = tx*4..+4

        float acc[8][4];
#pragma unroll
        for (int i = 0; i < 8; i++)
#pragma unroll
            for (int jj = 0; jj < 4; jj++) acc[i][jj] = 0.0f;

        // prologue: k-tile 0 -> buffer 0
        {
            float4 va = *(const float4*)(Arow + lkq * 4);
            float4 vb = *(const float4*)(Brow + lkq * 4);
            As[(lkq*4+0)*128 + lrow] = va.x; As[(lkq*4+1)*128 + lrow] = va.y;
            As[(lkq*4+2)*128 + lrow] = va.z; As[(lkq*4+3)*128 + lrow] = va.w;
            Bs[(lkq*4+0)*128 + lrow] = vb.x; Bs[(lkq*4+1)*128 + lrow] = vb.y;
            Bs[(lkq*4+2)*128 + lrow] = vb.z; Bs[(lkq*4+3)*128 + lrow] = vb.w;
        }
        __syncthreads();

        for (int kt = 0; kt < EMB / 16; kt++) {
            int p = kt & 1;
            float4 va, vb;
            if (kt < EMB / 16 - 1) {
                int k0 = (kt + 1) * 16;
                va = *(const float4*)(Arow + k0 + lkq * 4);
                vb = *(const float4*)(Brow + k0 + lkq * 4);
            }
            const float4* A4 = (const float4*)(As + p * 2048);
            const float4* B4 = (const float4*)(Bs + p * 2048);
#pragma unroll
            for (int k = 0; k < 16; k++) {
                float4 av0 = A4[k * 32 + ty * 2];
                float4 av1 = A4[k * 32 + ty * 2 + 1];
                float4 bv  = B4[k * 32 + tx];
                float aa[8] = {av0.x, av0.y, av0.z, av0.w, av1.x, av1.y, av1.z, av1.w};
                float bb[4] = {bv.x, bv.y, bv.z, bv.w};
#pragma unroll
                for (int i = 0; i < 8; i++)
#pragma unroll
                    for (int jj = 0; jj < 4; jj++) acc[i][jj] += aa[i] * bb[jj];
            }
            if (kt < EMB / 16 - 1) {
                int q = 1 - p;
                float* Aq = As + q * 2048;
                float* Bq = Bs + q * 2048;
                __syncthreads();
                Aq[(lkq*4+0)*128 + lrow] = va.x; Aq[(lkq*4+1)*128 + lrow] = va.y;
                Aq[(lkq*4+2)*128 + lrow] = va.z; Aq[(lkq*4+3)*128 + lrow] = va.w;
                Bq[(lkq*4+0)*128 + lrow] = vb.x; Bq[(lkq*4+1)*128 + lrow] = vb.y;
                Bq[(lkq*4+2)*128 + lrow] = vb.z; Bq[(lkq*4+3)*128 + lrow] = vb.w;
                __syncthreads();
            }
        }

        // epilogue: bias + store
        float4 bias;
        {
            int n = n0 + tx * 4;
            bias.x = b1[n+0] + b2[n+0]; bias.y = b1[n+1] + b2[n+1];
            bias.z = b1[n+2] + b2[n+2]; bias.w = b1[n+3] + b2[n+3];
        }
#pragma unroll
        for (int i = 0; i < 8; i++) {
            int m = m0 + ty * 8 + i;
            float4 o;
            o.x = acc[i][0] + bias.x; o.y = acc[i][1] + bias.y;
            o.z = acc[i][2] + bias.z; o.w = acc[i][3] + bias.w;
            *(float4*)(Gp + (size_t)m * G4 + n0 + tx * 4) = o;
        }
        __threadfence();
        __syncthreads();
        if (tid == 0) red_rel_add(&d_cnt[dir][tblk]);
    }
}

// -------------------- kernel: output projection feats = [hf|hb] @ Wout^T ----
__global__ void k_feats(const float* __restrict__ Wout,
                        const float* __restrict__ bout) {
    int t = blockIdx.x;
    int n = threadIdx.x >> 5;              // 5 warps -> 5 tags
    int lane = threadIdx.x & 31;
    const float* hf = d_h[0] + (size_t)t * H2;
    const float* hb = d_h[1] + (size_t)(TT - 1 - t) * H2;
    float s = 0.0f;
    const float* Wn = Wout + (size_t)n * (2 * H2);
#pragma unroll 4
    for (int k = lane; k < H2; k += 32) s += Wn[k] * hf[k];
#pragma unroll 4
    for (int k = lane; k < H2; k += 32) s += Wn[H2 + k] * hb[k];
#pragma unroll
    for (int off = 16; off > 0; off >>= 1) s += __shfl_xor_sync(0xffffffffu, s, off);
    if (lane == 0) d_feats[t * NTAGS + n] = s + bout[n];
}

// -------------------- kernel: Viterbi + backtrace (single CTA) --------------
__global__ void k_viterbi(const float* __restrict__ trans,
                          float* __restrict__ out, int out_size) {
    extern __shared__ float smem[];
    float* sfeat = smem;                                      // TT*NTAGS floats
    unsigned char* sbp = (unsigned char*)(smem + TT * NTAGS); // TT*NTAGS bytes
    __shared__ float fv[NTAGS];
    __shared__ float fvn[NTAGS];

    int tid = threadIdx.x;
    const float4* d4 = (const float4*)d_feats;
    float4* s4 = (float4*)sfeat;
    for (int i = tid; i < (TT * NTAGS) / 4; i += blockDim.x) s4[i] = d4[i];
    __syncthreads();

    if (tid < 32) {
        int n = tid;
        float tr[NTAGS];
        if (n < NTAGS) {
#pragma unroll
            for (int p = 0; p < NTAGS; p++) tr[p] = trans[n * NTAGS + p];
            fv[n] = (n == START) ? 0.0f : NEGV;
        }
        __syncwarp();
        for (int t = 0; t < TT; t++) {
            if (n < NTAGS) {
                float best = fv[0] + tr[0];
                int bp = 0;
#pragma unroll
                for (int p = 1; p < NTAGS; p++) {
                    float s = fv[p] + tr[p];
                    if (s > best) { best = s; bp = p; }
                }
                fvn[n] = best + sfeat[t * NTAGS + n];
                sbp[t * NTAGS + n] = (unsigned char)bp;
            }
            __syncwarp();
            if (n < NTAGS) fv[n] = fvn[n];
            __syncwarp();
        }
        if (n == 0) {
            float best = fv[0] + trans[STOP * NTAGS + 0];
            int bt = 0;
#pragma unroll
            for (int p = 1; p < NTAGS; p++) {
                float s = fv[p] + trans[STOP * NTAGS + p];
                if (s > best) { best = s; bt = p; }
            }
            if (out_size > 0) out[0] = best;
            int tag = bt;
            if (1 + (TT - 1) < out_size) out[1 + (TT - 1)] = (float)tag;
            for (int t = TT - 1; t >= 1; t--) {
                tag = sbp[t * NTAGS + tag];
                if (t < out_size) out[t] = (float)tag;
            }
        }
    }
}

// -------------------- launcher ----------------------------------------------
extern "C" void kernel_launch(void* const* d_in, const int* in_sizes, int n_in,
                              void* d_out, int out_size) {
    const int*   sent  = (const int*)d_in[0];
    const float* h0    = (const float*)d_in[1];
    const float* c0    = (const float*)d_in[2];
    const float* embed = (const float*)d_in[3];
    const float* Wih_f = (const float*)d_in[4];
    const float* Whh_f = (const float*)d_in[5];
    const float* bih_f = (const float*)d_in[6];
    const float* bhh_f = (const float*)d_in[7];
    const float* Wih_b = (const float*)d_in[8];
    const float* Whh_b = (const float*)d_in[9];
    const float* bih_b = (const float*)d_in[10];
    const float* bhh_b = (const float*)d_in[11];
    const float* Wout  = (const float*)d_in[12];
    const float* bout  = (const float*)d_in[13];
    const float* trans = (const float*)d_in[14];
    float* out = (float*)d_out;

    k_init<<<2048, 512>>>();
    int nblocks = 2 * NCTA + (TT / CHUNK) * NBLK * 2;   // 64 + 1024 = 1088
    k_main<<<nblocks, 512>>>(sent, embed,
                             Wih_f, Whh_f, bih_f, bhh_f,
                             Wih_b, Whh_b, bih_b, bhh_b, h0, c0);
    k_feats<<<TT, 160>>>(Wout, bout);

    int vit_smem = TT * NTAGS * (int)sizeof(float) + TT * NTAGS;  // 102400 B
    cudaFuncSetAttribute(k_viterbi, cudaFuncAttributeMaxDynamicSharedMemorySize,
                         vit_smem);
    k_viterbi<<<1, 128, vit_smem>>>(trans, out, out_size);
}

// round 5
// speedup vs baseline: 1.3258x; 1.3258x over previous
#include <cuda_runtime.h>

// Problem constants
#define TT    4096
#define EMB   1024
#define H2    512
#define G4    2048       // 4 * H2
#define NTAGS 5
#define START 3
#define STOP  4
#define NEGV  -10000.0f

// Recurrence: 64 CTAs per direction, 8 hidden units (32 gate rows) each
#define NCTA   64
#define HPER   8
#define SENTB  0x7FC00000u    // NaN sentinel bit pattern

// -------------------- scratch (static device globals; no allocs) ------------
__device__ float d_G[2][TT * G4];         // input-gate preactivations (64 MB)
__device__ float d_h[2][TT * H2];         // hidden states (16 MB), sentinel-init
__device__ float d_feats[TT * NTAGS];     // tag scores

// -------------------- helpers ----------------------------------------------
__device__ __forceinline__ float4 ld_acq_v4(const float* p) {
    float4 v;
    asm volatile("ld.acquire.gpu.global.v4.f32 {%0,%1,%2,%3}, [%4];"
                 : "=f"(v.x), "=f"(v.y), "=f"(v.z), "=f"(v.w) : "l"(p) : "memory");
    return v;
}
__device__ __forceinline__ void st_rel_v4(float* p, float4 v) {
    asm volatile("st.release.gpu.global.v4.f32 [%0], {%1,%2,%3,%4};"
                 :: "l"(p), "f"(v.x), "f"(v.y), "f"(v.z), "f"(v.w) : "memory");
}
__device__ __forceinline__ float tanh_fast(float x) {
    float y;
    asm("tanh.approx.f32 %0, %1;" : "=f"(y) : "f"(x));
    return y;
}
__device__ __forceinline__ float sigmoid_fast(float x) {
    return fmaf(0.5f, tanh_fast(0.5f * x), 0.5f);
}

// -------------------- kernel: sentinel-init d_h ------------------------------
// d_h = 2*4096*512 floats = 1,048,576 uint4
__global__ void k_init() {
    int i = blockIdx.x * blockDim.x + threadIdx.x;
    uint4 s; s.x = SENTB; s.y = SENTB; s.z = SENTB; s.w = SENTB;
    ((uint4*)d_h)[i] = s;
}

// -------------------- kernel: input GEMM  G = embed[sent] @ Wih^T + bias ----
// C tile 128x128, K tile 16, 256 threads, 8x8 blocking, double-buffered smem,
// embedding gather fused into the A load. dir==1 reads tokens in reverse.
__global__ __launch_bounds__(256) void k_gemm(
    const int*   __restrict__ sent, const float* __restrict__ embed,
    const float* __restrict__ Wf, const float* __restrict__ Wb,
    const float* __restrict__ bihf, const float* __restrict__ bhhf,
    const float* __restrict__ bihb, const float* __restrict__ bhhb) {
    int dir = blockIdx.z;
    const float* W  = dir ? Wb   : Wf;
    const float* b1 = dir ? bihb : bihf;
    const float* b2 = dir ? bhhb : bhhf;
    float* Gp = d_G[dir];

    __shared__ float As[2][16 * 128];
    __shared__ float Bs[2][16 * 128];

    int tid = threadIdx.x;
    int m0 = blockIdx.y * 128;
    int n0 = blockIdx.x * 128;
    int ty = tid >> 4, tx = tid & 15;

    // loader slots: f = tid + h*256, row = f>>2, kq = f&3
    int lrow[2], lkq[2];
    const float* Arow[2];
    const float* Brow[2];
#pragma unroll
    for (int h = 0; h < 2; h++) {
        int f = tid + h * 256;
        lrow[h] = f >> 2; lkq[h] = f & 3;
        int srcRow = m0 + lrow[h];
        if (dir) srcRow = TT - 1 - srcRow;
        int token = sent[srcRow];
        Arow[h] = embed + (size_t)token * EMB;
        Brow[h] = W + (size_t)(n0 + lrow[h]) * EMB;
    }

    float acc[8][8];
#pragma unroll
    for (int i = 0; i < 8; i++)
#pragma unroll
        for (int j = 0; j < 8; j++) acc[i][j] = 0.0f;

    // prologue: k-tile 0 -> buffer 0
#pragma unroll
    for (int h = 0; h < 2; h++) {
        float4 va = *(const float4*)(Arow[h] + lkq[h] * 4);
        float4 vb = *(const float4*)(Brow[h] + lkq[h] * 4);
        As[0][(lkq[h]*4+0)*128 + lrow[h]] = va.x;
        As[0][(lkq[h]*4+1)*128 + lrow[h]] = va.y;
        As[0][(lkq[h]*4+2)*128 + lrow[h]] = va.z;
        As[0][(lkq[h]*4+3)*128 + lrow[h]] = va.w;
        Bs[0][(lkq[h]*4+0)*128 + lrow[h]] = vb.x;
        Bs[0][(lkq[h]*4+1)*128 + lrow[h]] = vb.y;
        Bs[0][(lkq[h]*4+2)*128 + lrow[h]] = vb.z;
        Bs[0][(lkq[h]*4+3)*128 + lrow[h]] = vb.w;
    }
    __syncthreads();

    for (int kt = 0; kt < EMB / 16; kt++) {
        int p = kt & 1;
        float4 va[2], vb[2];
        if (kt < EMB / 16 - 1) {
            int k0 = (kt + 1) * 16;
#pragma unroll
            for (int h = 0; h < 2; h++) {
                va[h] = *(const float4*)(Arow[h] + k0 + lkq[h] * 4);
                vb[h] = *(const float4*)(Brow[h] + k0 + lkq[h] * 4);
            }
        }
#pragma unroll
        for (int k = 0; k < 16; k++) {
            float a[8], bb[8];
#pragma unroll
            for (int i = 0; i < 8; i++) a[i]  = As[p][k * 128 + ty * 8 + i];
#pragma unroll
            for (int j = 0; j < 8; j++) bb[j] = Bs[p][k * 128 + tx * 8 + j];
#pragma unroll
            for (int i = 0; i < 8; i++)
#pragma unroll
                for (int j = 0; j < 8; j++) acc[i][j] += a[i] * bb[j];
        }
        if (kt < EMB / 16 - 1) {
            int q = 1 - p;
            __syncthreads();
#pragma unroll
            for (int h = 0; h < 2; h++) {
                As[q][(lkq[h]*4+0)*128 + lrow[h]] = va[h].x;
                As[q][(lkq[h]*4+1)*128 + lrow[h]] = va[h].y;
                As[q][(lkq[h]*4+2)*128 + lrow[h]] = va[h].z;
                As[q][(lkq[h]*4+3)*128 + lrow[h]] = va[h].w;
                Bs[q][(lkq[h]*4+0)*128 + lrow[h]] = vb[h].x;
                Bs[q][(lkq[h]*4+1)*128 + lrow[h]] = vb[h].y;
                Bs[q][(lkq[h]*4+2)*128 + lrow[h]] = vb[h].z;
                Bs[q][(lkq[h]*4+3)*128 + lrow[h]] = vb[h].w;
            }
            __syncthreads();
        }
    }

    float bias[8];
#pragma unroll
    for (int j = 0; j < 8; j++) {
        int n = n0 + tx * 8 + j;
        bias[j] = b1[n] + b2[n];
    }
#pragma unroll
    for (int i = 0; i < 8; i++) {
        int m = m0 + ty * 8 + i;
#pragma unroll
        for (int j = 0; j < 8; j++) {
            int n = n0 + tx * 8 + j;
            Gp[(size_t)m * G4 + n] = acc[i][j] + bias[j];
        }
    }
}

// -------------------- kernel: persistent LSTM recurrence --------------------
// grid = 128 CTAs (64/dir), 512 threads. CTA owns 8 hidden units = 32 gate
// rows; Whh slice in registers. Sync: h data itself is the flag — d_h is
// sentinel-initialized; producers st.release.v4, consumers ld.acquire.v4 poll.
__global__ void __launch_bounds__(512, 1) k_recur(
    const float* __restrict__ Whh_f, const float* __restrict__ Whh_b,
    const float* __restrict__ h0, const float* __restrict__ c0) {
    int dir   = blockIdx.x >> 6;
    int slice = blockIdx.x & 63;
    int hbase = slice * HPER;
    const float* Whh = dir ? Whh_b : Whh_f;
    const float* Gd  = d_G[dir];
    float* hout = d_h[dir];

    int tid = threadIdx.x;
    int warp = tid >> 5, lane = tid & 31;

    // this warp's 2 gate rows
    int rows[2];
#pragma unroll
    for (int i = 0; i < 2; i++) {
        int r = 2 * warp + i;                    // 0..31 == g*8 + j
        rows[i] = (r >> 3) * H2 + hbase + (r & 7);
    }
    // Whh slice: k = q*128 + lane*4 (+m)
    float whh[2][16];
#pragma unroll
    for (int i = 0; i < 2; i++)
#pragma unroll
        for (int q = 0; q < 4; q++) {
            float4 v = *(const float4*)(Whh + (size_t)rows[i] * H2 + q * 128 + lane * 4);
            whh[i][q*4+0] = v.x; whh[i][q*4+1] = v.y;
            whh[i][q*4+2] = v.z; whh[i][q*4+3] = v.w;
        }

    __shared__ __align__(16) float sh[H2];
    __shared__ float rec_s[32];

    float cj = 0.0f;
    bool act = (warp == 0) && (lane < HPER);
    if (act) cj = c0[dir * H2 + hbase + lane];

    for (int t = 0; t < TT; t++) {
        // G(t) prefetch (issues before the poll; overlaps it)
        float gv0 = 0.f, gv1 = 0.f, gv2 = 0.f, gv3 = 0.f;
        if (act) {
            const float* Gt = Gd + (size_t)t * G4 + hbase + lane;
            gv0 = Gt[0]; gv1 = Gt[H2]; gv2 = Gt[2 * H2]; gv3 = Gt[3 * H2];
        }

        // obtain h(t-1): poll the data itself (one L2 trip)
        if (t == 0) {
            sh[tid] = h0[dir * H2 + tid];
        } else if (tid < 128) {
            const float* p = hout + (size_t)(t - 1) * H2 + tid * 4;
            float4 v;
            do { v = ld_acq_v4(p); } while (__float_as_uint(v.x) == SENTB);
            *(float4*)(sh + tid * 4) = v;
        }
        __syncthreads();

        // recurrent GEMV
        float a0 = 0.0f, a1 = 0.0f;
#pragma unroll
        for (int q = 0; q < 4; q++) {
            float4 hv = *(const float4*)(sh + q * 128 + lane * 4);
            a0 += whh[0][q*4+0]*hv.x + whh[0][q*4+1]*hv.y + whh[0][q*4+2]*hv.z + whh[0][q*4+3]*hv.w;
            a1 += whh[1][q*4+0]*hv.x + whh[1][q*4+1]*hv.y + whh[1][q*4+2]*hv.z + whh[1][q*4+3]*hv.w;
        }
#pragma unroll
        for (int off = 16; off > 0; off >>= 1) {
            a0 += __shfl_xor_sync(0xffffffffu, a0, off);
            a1 += __shfl_xor_sync(0xffffffffu, a1, off);
        }
        if (lane == 0) { rec_s[2*warp] = a0; rec_s[2*warp+1] = a1; }
        __syncthreads();

        // activation + release-store (warp 0)
        if (warp == 0) {
            float hj = 0.0f;
            if (lane < HPER) {
                float gi = rec_s[0*HPER + lane] + gv0;
                float gf = rec_s[1*HPER + lane] + gv1;
                float gg = rec_s[2*HPER + lane] + gv2;
                float go = rec_s[3*HPER + lane] + gv3;
                cj = sigmoid_fast(gf) * cj + sigmoid_fast(gi) * tanh_fast(gg);
                hj = sigmoid_fast(go) * tanh_fast(cj);
            }
            int base = lane & ~3;
            float4 o;
            o.x = __shfl_sync(0xffffffffu, hj, base + 0);
            o.y = __shfl_sync(0xffffffffu, hj, base + 1);
            o.z = __shfl_sync(0xffffffffu, hj, base + 2);
            o.w = __shfl_sync(0xffffffffu, hj, base + 3);
            if ((lane & 3) == 0 && lane < HPER)
                st_rel_v4(hout + (size_t)t * H2 + hbase + lane, o);
        }
    }
}

// -------------------- kernel: output projection feats = [hf|hb] @ Wout^T ----
__global__ void k_feats(const float* __restrict__ Wout,
                        const float* __restrict__ bout) {
    int t = blockIdx.x;
    int n = threadIdx.x >> 5;              // 5 warps -> 5 tags
    int lane = threadIdx.x & 31;
    const float* hf = d_h[0] + (size_t)t * H2;
    const float* hb = d_h[1] + (size_t)(TT - 1 - t) * H2;
    float s = 0.0f;
    const float* Wn = Wout + (size_t)n * (2 * H2);
#pragma unroll 4
    for (int k = lane; k < H2; k += 32) s += Wn[k] * hf[k];
#pragma unroll 4
    for (int k = lane; k < H2; k += 32) s += Wn[H2 + k] * hb[k];
#pragma unroll
    for (int off = 16; off > 0; off >>= 1) s += __shfl_xor_sync(0xffffffffu, s, off);
    if (lane == 0) d_feats[t * NTAGS + n] = s + bout[n];
}

// -------------------- kernel: Viterbi + backtrace (single CTA) --------------
// Forward scan: lanes 0-4 own one tag each; fv register-resident, 5-shuffle
// all-to-all per step; backpointers to SMEM; scalar backtrace.
__global__ void k_viterbi(const float* __restrict__ trans,
                          float* __restrict__ out, int out_size) {
    extern __shared__ float smem[];
    float* sfeat = smem;                                      // TT*NTAGS floats
    unsigned char* sbp = (unsigned char*)(smem + TT * NTAGS); // TT*NTAGS bytes

    int tid = threadIdx.x;
    const float4* d4 = (const float4*)d_feats;
    float4* s4 = (float4*)sfeat;
    for (int i = tid; i < (TT * NTAGS) / 4; i += blockDim.x) s4[i] = d4[i];
    __syncthreads();

    if (tid < 32) {
        int lane = tid;
        int n = lane < NTAGS ? lane : NTAGS - 1;
        float tr[NTAGS];
#pragma unroll
        for (int p = 0; p < NTAGS; p++) tr[p] = trans[n * NTAGS + p];
        float f0 = (0 == START) ? 0.0f : NEGV;
        float f1 = (1 == START) ? 0.0f : NEGV;
        float f2 = (2 == START) ? 0.0f : NEGV;
        float f3 = (3 == START) ? 0.0f : NEGV;
        float f4 = (4 == START) ? 0.0f : NEGV;

        for (int t = 0; t < TT; t++) {
            float feat = sfeat[t * NTAGS + n];
            float best = f0 + tr[0]; int bp = 0;
            float v;
            v = f1 + tr[1]; if (v > best) { best = v; bp = 1; }
            v = f2 + tr[2]; if (v > best) { best = v; bp = 2; }
            v = f3 + tr[3]; if (v > best) { best = v; bp = 3; }
            v = f4 + tr[4]; if (v > best) { best = v; bp = 4; }
            float fn = best + feat;
            f0 = __shfl_sync(0xffffffffu, fn, 0);
            f1 = __shfl_sync(0xffffffffu, fn, 1);
            f2 = __shfl_sync(0xffffffffu, fn, 2);
            f3 = __shfl_sync(0xffffffffu, fn, 3);
            f4 = __shfl_sync(0xffffffffu, fn, 4);
            if (lane < NTAGS) sbp[t * NTAGS + lane] = (unsigned char)bp;
        }

        if (lane == 0) {
            float fv[NTAGS] = {f0, f1, f2, f3, f4};
            float best = fv[0] + trans[STOP * NTAGS + 0];
            int bt = 0;
#pragma unroll
            for (int p = 1; p < NTAGS; p++) {
                float s = fv[p] + trans[STOP * NTAGS + p];
                if (s > best) { best = s; bt = p; }
            }
            if (out_size > 0) out[0] = best;
            int tag = bt;
            if (1 + (TT - 1) < out_size) out[1 + (TT - 1)] = (float)tag;
            for (int t = TT - 1; t >= 1; t--) {
                tag = sbp[t * NTAGS + tag];
                if (t < out_size) out[t] = (float)tag;
            }
        }
    }
}

// -------------------- launcher ----------------------------------------------
extern "C" void kernel_launch(void* const* d_in, const int* in_sizes, int n_in,
                              void* d_out, int out_size) {
    const int*   sent  = (const int*)d_in[0];
    const float* h0    = (const float*)d_in[1];
    const float* c0    = (const float*)d_in[2];
    const float* embed = (const float*)d_in[3];
    const float* Wih_f = (const float*)d_in[4];
    const float* Whh_f = (const float*)d_in[5];
    const float* bih_f = (const float*)d_in[6];
    const float* bhh_f = (const float*)d_in[7];
    const float* Wih_b = (const float*)d_in[8];
    const float* Whh_b = (const float*)d_in[9];
    const float* bih_b = (const float*)d_in[10];
    const float* bhh_b = (const float*)d_in[11];
    const float* Wout  = (const float*)d_in[12];
    const float* bout  = (const float*)d_in[13];
    const float* trans = (const float*)d_in[14];
    float* out = (float*)d_out;

    k_init<<<2048, 512>>>();
    dim3 gg(G4 / 128, TT / 128, 2);
    k_gemm<<<gg, 256>>>(sent, embed, Wih_f, Wih_b,
                        bih_f, bhh_f, bih_b, bhh_b);
    k_recur<<<2 * NCTA, 512>>>(Whh_f, Whh_b, h0, c0);
    k_feats<<<TT, 160>>>(Wout, bout);

    int vit_smem = TT * NTAGS * (int)sizeof(float) + TT * NTAGS;  // 102400 B
    cudaFuncSetAttribute(k_viterbi, cudaFuncAttributeMaxDynamicSharedMemorySize,
                         vit_smem);
    k_viterbi<<<1, 128, vit_smem>>>(trans, out, out_size);
}